// round 5
// baseline (speedup 1.0000x reference)
#include <cuda_runtime.h>
#include <math.h>

// Problem constants
#define B_      4096
#define S_SRC_  32
#define S_TGT_  32
#define E_      128
#define H_      512
#define V_TGT_  128
#define G4H_    2048          // 4*H
#define KCAT_   640           // E + H
#define SOS_    1

// ---------------------------------------------------------------------------
// Device scratch (static — no allocations allowed)
// ---------------------------------------------------------------------------
__device__ __align__(16) float g_Wcat_enc[KCAT_ * G4H_];   // [k][gate*H+n]
__device__ __align__(16) float g_Wcat_dec[KCAT_ * G4H_];
__device__ __align__(16) float g_bias_enc[G4H_];
__device__ __align__(16) float g_bias_dec[G4H_];
__device__ __align__(16) float g_WoutT[H_ * V_TGT_];       // [k][v]
__device__ __align__(16) float g_h[2][B_ * H_];            // ping-pong hidden
__device__ __align__(16) float g_c[B_ * H_];               // cell state
__device__ __align__(16) float g_hs[S_TGT_ * B_ * H_];     // decoder hiddens

// ---------------------------------------------------------------------------
// Prep: pack [Wih | Whh]^T, sum biases, transpose W_out, zero h0/c0
// ---------------------------------------------------------------------------
__global__ void prep_kernel(const float* __restrict__ eWih, const float* __restrict__ eWhh,
                            const float* __restrict__ eBih, const float* __restrict__ eBhh,
                            const float* __restrict__ dWih, const float* __restrict__ dWhh,
                            const float* __restrict__ dBih, const float* __restrict__ dBhh,
                            const float* __restrict__ Wout)
{
    int tid = blockIdx.x * blockDim.x + threadIdx.x;
    int stride = gridDim.x * blockDim.x;

    for (int i = tid; i < KCAT_ * G4H_; i += stride) {
        int k = i / G4H_;
        int r = i % G4H_;                 // r = gate*H + n (PyTorch [i,f,g,o] layout)
        g_Wcat_enc[i] = (k < E_) ? eWih[r * E_ + k] : eWhh[r * H_ + (k - E_)];
        g_Wcat_dec[i] = (k < E_) ? dWih[r * E_ + k] : dWhh[r * H_ + (k - E_)];
    }
    for (int i = tid; i < G4H_; i += stride) {
        g_bias_enc[i] = eBih[i] + eBhh[i];
        g_bias_dec[i] = dBih[i] + dBhh[i];
    }
    for (int i = tid; i < H_ * V_TGT_; i += stride) {
        int k = i / V_TGT_, v = i % V_TGT_;
        g_WoutT[i] = Wout[v * H_ + k];
    }
    for (int i = tid; i < B_ * H_; i += stride) {
        g_h[0][i] = 0.0f;
        g_c[i]    = 0.0f;
    }
}

// ---------------------------------------------------------------------------
// Fused LSTM step: gates = [x_t | h_prev] @ Wcat  (+bias)  -> activations ->
// h/c update (masked for encoder). One launch per timestep.
//   Tile: BM=128 batch rows, BN=32 h-cols (x4 gates = 128 weight cols), BK=16.
//   256 threads, 64 fp32 accumulators each.
// ---------------------------------------------------------------------------
template<bool IS_ENC>
__global__ __launch_bounds__(256, 2)
void lstm_step_kernel(int step, int par_src,
                      const int* __restrict__ seq,       // src_seq / tgt_seq
                      const int* __restrict__ lengths,   // src_lengths (enc only)
                      const float* __restrict__ emb)     // emb_src / emb_tgt
{
    __shared__ float a_s[16][128];     // [k][m]
    __shared__ float w_s[16][128];     // [k][c], c = gate*32 + j (j = local n)
    __shared__ int   tok_s[128];

    const float* __restrict__ Wcat = IS_ENC ? g_Wcat_enc : g_Wcat_dec;
    const float* __restrict__ bias = IS_ENC ? g_bias_enc : g_bias_dec;
    const float* __restrict__ h_src = g_h[par_src];
    float* __restrict__ h_dst = g_h[par_src ^ 1];

    const int t  = threadIdx.x;
    const int m0 = blockIdx.x * 128;
    const int n0 = blockIdx.y * 32;

    // token table for this block's 128 batch rows
    if (t < 128) {
        int m = m0 + t;
        int tok;
        if (IS_ENC) tok = seq[m * S_SRC_ + step];
        else        tok = (step == 0) ? SOS_ : seq[m * S_TGT_ + step - 1];
        tok_s[t] = tok;
    }
    __syncthreads();

    // load-thread mapping
    const int lm = t >> 1;                  // 0..127 : A row
    const int lh = t & 1;                   // A k-half (8 floats)
    const int wk = t >> 4;                  // 0..15  : W k row
    const int wl = t & 15;                  // W lane -> 8 cols
    const int wg  = wl >> 2;                // gate 0..3
    const int wj0 = (wl & 3) * 8;           // local n offset

    // compute-thread mapping
    const int tr = t & 15;                  // rows tr*8 .. tr*8+7
    const int tc = t >> 4;                  // n pair: tc*2, tc*2+1

    float acc[8][2][4];
    #pragma unroll
    for (int r = 0; r < 8; r++)
        #pragma unroll
        for (int nn = 0; nn < 2; nn++)
            #pragma unroll
            for (int g = 0; g < 4; g++) acc[r][nn][g] = 0.0f;

    float4 sa0, sa1, sw0, sw1;

    // prologue: stage tile kt=0 (k0=0 -> embedding region)
    {
        const float* ap = emb + tok_s[lm] * E_ + lh * 8;
        sa0 = *(const float4*)ap;
        sa1 = *(const float4*)(ap + 4);
        const float* wp = Wcat + (0 + wk) * G4H_ + wg * H_ + n0 + wj0;
        sw0 = *(const float4*)wp;
        sw1 = *(const float4*)(wp + 4);
    }

    const int NKT = KCAT_ / 16;   // 40
    for (int kt = 0; kt < NKT; kt++) {
        __syncthreads();
        {   // commit staged tile to smem
            int kb = lh * 8;
            a_s[kb + 0][lm] = sa0.x; a_s[kb + 1][lm] = sa0.y;
            a_s[kb + 2][lm] = sa0.z; a_s[kb + 3][lm] = sa0.w;
            a_s[kb + 4][lm] = sa1.x; a_s[kb + 5][lm] = sa1.y;
            a_s[kb + 6][lm] = sa1.z; a_s[kb + 7][lm] = sa1.w;
            *(float4*)&w_s[wk][wl * 8]     = sw0;
            *(float4*)&w_s[wk][wl * 8 + 4] = sw1;
        }
        __syncthreads();

        // prefetch next tile (overlaps with compute below)
        if (kt + 1 < NKT) {
            int k0 = (kt + 1) * 16;
            if (k0 < E_) {
                const float* ap = emb + tok_s[lm] * E_ + k0 + lh * 8;
                sa0 = *(const float4*)ap;
                sa1 = *(const float4*)(ap + 4);
            } else {
                const float* ap = h_src + (m0 + lm) * H_ + (k0 - E_) + lh * 8;
                sa0 = *(const float4*)ap;
                sa1 = *(const float4*)(ap + 4);
            }
            const float* wp = Wcat + (k0 + wk) * G4H_ + wg * H_ + n0 + wj0;
            sw0 = *(const float4*)wp;
            sw1 = *(const float4*)(wp + 4);
        }

        // FFMA mainloop over this BK=16 tile
        #pragma unroll
        for (int kk = 0; kk < 16; kk++) {
            float af[8];
            float4 v0 = *(const float4*)&a_s[kk][tr * 8];
            float4 v1 = *(const float4*)&a_s[kk][tr * 8 + 4];
            af[0] = v0.x; af[1] = v0.y; af[2] = v0.z; af[3] = v0.w;
            af[4] = v1.x; af[5] = v1.y; af[6] = v1.z; af[7] = v1.w;
            float wf[4][2];
            #pragma unroll
            for (int g = 0; g < 4; g++) {
                float2 w2 = *(const float2*)&w_s[kk][g * 32 + tc * 2];
                wf[g][0] = w2.x; wf[g][1] = w2.y;
            }
            #pragma unroll
            for (int r = 0; r < 8; r++)
                #pragma unroll
                for (int nn = 0; nn < 2; nn++)
                    #pragma unroll
                    for (int g = 0; g < 4; g++)
                        acc[r][nn][g] += af[r] * wf[g][nn];
        }
    }

    // ------------------ epilogue: LSTM cell ------------------
    #pragma unroll
    for (int r = 0; r < 8; r++) {
        int m = m0 + tr * 8 + r;
        int len = 0;
        if (IS_ENC) len = lengths[m];
        #pragma unroll
        for (int nn = 0; nn < 2; nn++) {
            int n = n0 + tc * 2 + nn;
            float gi = acc[r][nn][0] + bias[n];
            float gf = acc[r][nn][1] + bias[H_ + n];
            float gg = acc[r][nn][2] + bias[2 * H_ + n];
            float go = acc[r][nn][3] + bias[3 * H_ + n];
            float i_ = 1.0f / (1.0f + expf(-gi));
            float f_ = 1.0f / (1.0f + expf(-gf));
            float g_ = tanhf(gg);
            float o_ = 1.0f / (1.0f + expf(-go));
            int idx = m * H_ + n;
            float c_old = g_c[idx];
            float c_new = f_ * c_old + i_ * g_;
            float h_new = o_ * tanhf(c_new);
            if (IS_ENC && step >= len) {      // pack_padded: freeze past length
                c_new = c_old;
                h_new = h_src[idx];
            }
            g_c[idx]   = c_new;
            h_dst[idx] = h_new;
            if (!IS_ENC) g_hs[step * (B_ * H_) + idx] = h_new;
        }
    }
}

// ---------------------------------------------------------------------------
// Logits: (B*T, H) @ (H, V) + b_out  ->  out[b][t][v]
//   Tile: BM=128, BN=128 (=V), BK=16, 256 threads, 64 accums/thread.
// ---------------------------------------------------------------------------
__global__ __launch_bounds__(256, 2)
void logits_kernel(const float* __restrict__ b_out, float* __restrict__ out)
{
    __shared__ float a_s[16][128];
    __shared__ float w_s[16][128];

    const int t  = threadIdx.x;
    const int m0 = blockIdx.x * 128;     // m = tt*B + b
    const int lm = t >> 1, lh = t & 1;
    const int wk = t >> 4, wl = t & 15;
    const int tr = t & 15, tc = t >> 4;

    float acc[8][8];
    #pragma unroll
    for (int r = 0; r < 8; r++)
        #pragma unroll
        for (int q = 0; q < 8; q++) acc[r][q] = 0.0f;

    float4 sa0, sa1, sw0, sw1;
    {
        const float* ap = g_hs + (m0 + lm) * H_ + lh * 8;
        sa0 = *(const float4*)ap; sa1 = *(const float4*)(ap + 4);
        const float* wp = g_WoutT + wk * V_TGT_ + wl * 8;
        sw0 = *(const float4*)wp; sw1 = *(const float4*)(wp + 4);
    }

    const int NKT = H_ / 16;  // 32
    for (int kt = 0; kt < NKT; kt++) {
        __syncthreads();
        {
            int kb = lh * 8;
            a_s[kb + 0][lm] = sa0.x; a_s[kb + 1][lm] = sa0.y;
            a_s[kb + 2][lm] = sa0.z; a_s[kb + 3][lm] = sa0.w;
            a_s[kb + 4][lm] = sa1.x; a_s[kb + 5][lm] = sa1.y;
            a_s[kb + 6][lm] = sa1.z; a_s[kb + 7][lm] = sa1.w;
            *(float4*)&w_s[wk][wl * 8]     = sw0;
            *(float4*)&w_s[wk][wl * 8 + 4] = sw1;
        }
        __syncthreads();
        if (kt + 1 < NKT) {
            int k0 = (kt + 1) * 16;
            const float* ap = g_hs + (m0 + lm) * H_ + k0 + lh * 8;
            sa0 = *(const float4*)ap; sa1 = *(const float4*)(ap + 4);
            const float* wp = g_WoutT + (k0 + wk) * V_TGT_ + wl * 8;
            sw0 = *(const float4*)wp; sw1 = *(const float4*)(wp + 4);
        }
        #pragma unroll
        for (int kk = 0; kk < 16; kk++) {
            float af[8], wf[8];
            float4 v0 = *(const float4*)&a_s[kk][tr * 8];
            float4 v1 = *(const float4*)&a_s[kk][tr * 8 + 4];
            af[0] = v0.x; af[1] = v0.y; af[2] = v0.z; af[3] = v0.w;
            af[4] = v1.x; af[5] = v1.y; af[6] = v1.z; af[7] = v1.w;
            float4 u0 = *(const float4*)&w_s[kk][tc * 8];
            float4 u1 = *(const float4*)&w_s[kk][tc * 8 + 4];
            wf[0] = u0.x; wf[1] = u0.y; wf[2] = u0.z; wf[3] = u0.w;
            wf[4] = u1.x; wf[5] = u1.y; wf[6] = u1.z; wf[7] = u1.w;
            #pragma unroll
            for (int r = 0; r < 8; r++)
                #pragma unroll
                for (int q = 0; q < 8; q++)
                    acc[r][q] += af[r] * wf[q];
        }
    }

    #pragma unroll
    for (int r = 0; r < 8; r++) {
        int m  = m0 + tr * 8 + r;
        int b  = m & (B_ - 1);
        int tt = m >> 12;                 // B_ = 2^12
        #pragma unroll
        for (int q = 0; q < 8; q++) {
            int v = tc * 8 + q;
            out[(b * S_TGT_ + tt) * V_TGT_ + v] = acc[r][q] + b_out[v];
        }
    }
}

// ---------------------------------------------------------------------------
// Launch
// ---------------------------------------------------------------------------
extern "C" void kernel_launch(void* const* d_in, const int* in_sizes, int n_in,
                              void* d_out, int out_size)
{
    (void)in_sizes; (void)n_in; (void)out_size;
    const int*   src_seq = (const int*)  d_in[0];
    const int*   src_len = (const int*)  d_in[1];
    const int*   tgt_seq = (const int*)  d_in[2];
    const float* emb_src = (const float*)d_in[3];
    const float* eWih    = (const float*)d_in[4];
    const float* eWhh    = (const float*)d_in[5];
    const float* eBih    = (const float*)d_in[6];
    const float* eBhh    = (const float*)d_in[7];
    const float* emb_tgt = (const float*)d_in[8];
    const float* dWih    = (const float*)d_in[9];
    const float* dWhh    = (const float*)d_in[10];
    const float* dBih    = (const float*)d_in[11];
    const float* dBhh    = (const float*)d_in[12];
    const float* Wout    = (const float*)d_in[13];
    const float* bout    = (const float*)d_in[14];
    float*       out     = (float*)d_out;

    prep_kernel<<<2048, 256>>>(eWih, eWhh, eBih, eBhh,
                               dWih, dWhh, dBih, dBhh, Wout);

    dim3 grid(B_ / 128, H_ / 32);   // (32, 16)
    for (int s = 0; s < S_SRC_; s++)
        lstm_step_kernel<true ><<<grid, 256>>>(s, s & 1, src_seq, src_len, emb_src);
    for (int tt = 0; tt < S_TGT_; tt++)
        lstm_step_kernel<false><<<grid, 256>>>(tt, tt & 1, tgt_seq, nullptr, emb_tgt);

    logits_kernel<<<(B_ * S_TGT_) / 128, 256>>>(bout, out);
}

// round 7
// speedup vs baseline: 2.7281x; 2.7281x over previous
#include <cuda_runtime.h>
#include <cuda_bf16.h>
#include <cstdint>
#include <math.h>

#define B_      4096
#define S_      32
#define E_      128
#define H_      512
#define V_TGT_  128
#define NCOL_   2048          // 4*H, gate-interleaved col' = h*4 + gate
#define KC_     640           // E + H
#define SOS_    1
#define NSTEP_  64
#define BH_     (B_ * H_)
#define XSTEP_  (B_ * E_)

#define BM_     128
#define BN_     128
#define BK_     64            // bf16 per K-tile (128 B rows)
#define NIT_    30            // 3 passes x (640/64)
#define STAGE_  32768         // A 16KB + W 16KB
#define SMEM_DYN_ (2 * STAGE_ + 1024)

// ---------------------------------------------------------------------------
// Device scratch (static; no allocations allowed)
// ---------------------------------------------------------------------------
__device__ __align__(256) __nv_bfloat16 g_Xhi[NSTEP_ * XSTEP_];
__device__ __align__(256) __nv_bfloat16 g_Xlo[NSTEP_ * XSTEP_];
__device__ __align__(256) __nv_bfloat16 g_Whi[2][NCOL_ * KC_];   // [dir][n'][k]
__device__ __align__(256) __nv_bfloat16 g_Wlo[2][NCOL_ * KC_];
__device__ __align__(256) float         g_bias[2][NCOL_];
__device__ __align__(256) __nv_bfloat16 g_hhi[2][BH_];
__device__ __align__(256) __nv_bfloat16 g_hlo[2][BH_];
__device__ __align__(256) float         g_c[BH_];
__device__ __align__(256) float         g_hs[S_ * BH_];
__device__ __align__(256) float         g_WoutT[H_ * V_TGT_];

// ---------------------------------------------------------------------------
__device__ __forceinline__ uint32_t smem_u32(const void* p) {
    uint32_t a;
    asm("{ .reg .u64 t; cvta.to.shared.u64 t, %1; cvt.u32.u64 %0, t; }" : "=r"(a) : "l"(p));
    return a;
}
__device__ __forceinline__ void cp16(uint32_t dst, const void* src) {
    asm volatile("cp.async.cg.shared.global [%0], [%1], 16;" :: "r"(dst), "l"(src));
}
__device__ __forceinline__ void ldm_x4(uint32_t* r, uint32_t addr) {
    asm volatile("ldmatrix.sync.aligned.m8n8.x4.shared.b16 {%0,%1,%2,%3}, [%4];"
        : "=r"(r[0]), "=r"(r[1]), "=r"(r[2]), "=r"(r[3]) : "r"(addr));
}
__device__ __forceinline__ void mma16816(float* c, const uint32_t* a, uint32_t b0, uint32_t b1) {
    asm volatile("mma.sync.aligned.m16n8k16.row.col.f32.bf16.bf16.f32 "
        "{%0,%1,%2,%3}, {%4,%5,%6,%7}, {%8,%9}, {%0,%1,%2,%3};"
        : "+f"(c[0]), "+f"(c[1]), "+f"(c[2]), "+f"(c[3])
        : "r"(a[0]), "r"(a[1]), "r"(a[2]), "r"(a[3]), "r"(b0), "r"(b1));
}
__device__ __forceinline__ float fsig(float x)  { return __fdividef(1.0f, 1.0f + __expf(-x)); }
__device__ __forceinline__ float ftanh(float x) { return 1.0f - __fdividef(2.0f, __expf(2.0f * x) + 1.0f); }

// ---------------------------------------------------------------------------
// Prep: hi/lo-split weights (gate-interleaved [n'][k]), pre-gathered hi/lo
// embedding slices for all 64 steps, summed biases, WoutT, zeroed state.
// ---------------------------------------------------------------------------
__global__ void prep_kernel(const int* __restrict__ src_seq, const int* __restrict__ tgt_seq,
                            const float* __restrict__ emb_src, const float* __restrict__ emb_tgt,
                            const float* __restrict__ eWih, const float* __restrict__ eWhh,
                            const float* __restrict__ eBih, const float* __restrict__ eBhh,
                            const float* __restrict__ dWih, const float* __restrict__ dWhh,
                            const float* __restrict__ dBih, const float* __restrict__ dBhh,
                            const float* __restrict__ Wout)
{
    const long long t0 = (long long)blockIdx.x * blockDim.x + threadIdx.x;
    const long long st = (long long)gridDim.x * blockDim.x;

    for (long long i = t0; i < (long long)NSTEP_ * XSTEP_; i += st) {
        int k = (int)(i & 127);
        long long sm = i >> 7;
        int m = (int)(sm & (B_ - 1));
        int s = (int)(sm >> 12);
        int tok; const float* emb;
        if (s < 32)       { tok = src_seq[m * S_ + s]; emb = emb_src; }
        else if (s == 32) { tok = SOS_;                emb = emb_tgt; }
        else              { tok = tgt_seq[m * S_ + (s - 33)]; emb = emb_tgt; }
        float v = emb[tok * E_ + k];
        __nv_bfloat16 hi = __float2bfloat16_rn(v);
        g_Xhi[i] = hi;
        g_Xlo[i] = __float2bfloat16_rn(v - __bfloat162float(hi));
    }
    for (long long i = t0; i < (long long)NCOL_ * KC_; i += st) {
        int np = (int)(i / KC_);
        int k  = (int)(i - (long long)np * KC_);
        int g = np & 3, n = np >> 2;
        int r = g * H_ + n;                       // PyTorch [i,f,g,o] gate layout
        float ve = (k < E_) ? eWih[r * E_ + k] : eWhh[r * H_ + (k - E_)];
        float vd = (k < E_) ? dWih[r * E_ + k] : dWhh[r * H_ + (k - E_)];
        __nv_bfloat16 he = __float2bfloat16_rn(ve);
        __nv_bfloat16 hd = __float2bfloat16_rn(vd);
        g_Whi[0][i] = he;  g_Wlo[0][i] = __float2bfloat16_rn(ve - __bfloat162float(he));
        g_Whi[1][i] = hd;  g_Wlo[1][i] = __float2bfloat16_rn(vd - __bfloat162float(hd));
    }
    for (long long i = t0; i < NCOL_; i += st) {
        int g = (int)i & 3, n = (int)i >> 2;
        int r = g * H_ + n;
        g_bias[0][i] = eBih[r] + eBhh[r];
        g_bias[1][i] = dBih[r] + dBhh[r];
    }
    for (long long i = t0; i < (long long)H_ * V_TGT_; i += st) {
        int k = (int)(i / V_TGT_), v = (int)(i % V_TGT_);
        g_WoutT[i] = Wout[v * H_ + k];
    }
    __nv_bfloat16 z = __float2bfloat16_rn(0.0f);
    for (long long i = t0; i < BH_; i += st) {
        g_hhi[0][i] = z;
        g_hlo[0][i] = z;
        g_c[i] = 0.0f;
    }
}

// ---------------------------------------------------------------------------
// Stage loader: stage in [0,30): pass = stage/10 (0:hi*hi 1:hi*lo 2:lo*hi)
// ---------------------------------------------------------------------------
__device__ __forceinline__ void load_stage(uint32_t sbase, int stage, int m0, int n0p, int tid,
    const __nv_bfloat16* __restrict__ Xhi, const __nv_bfloat16* __restrict__ Xlo,
    const __nv_bfloat16* __restrict__ hhi_s, const __nv_bfloat16* __restrict__ hlo_s,
    const __nv_bfloat16* __restrict__ Whi,  const __nv_bfloat16* __restrict__ Wlo)
{
    int pass = stage / 10;
    int kt   = stage - pass * 10;
    int kofs = kt * BK_;
    const __nv_bfloat16* Xs = (pass == 2) ? Xlo : Xhi;
    const __nv_bfloat16* Hs = (pass == 2) ? hlo_s : hhi_s;
    const __nv_bfloat16* Wp = (pass == 1) ? Wlo : Whi;
    uint32_t Ab = sbase, Wb = sbase + 16384;

    #pragma unroll
    for (int i = 0; i < 4; i++) {                 // A: 128 rows x 8 x 16B
        int idx = tid + i * 256;
        int row = idx >> 3, c = idx & 7;
        const void* src = (kt < 2)
            ? (const void*)(Xs + (size_t)(m0 + row) * E_ + kofs + c * 8)
            : (const void*)(Hs + (size_t)(m0 + row) * H_ + (kofs - E_) + c * 8);
        cp16(Ab + row * 128 + (uint32_t)((c * 16) ^ ((row & 7) << 4)), src);
    }
    #pragma unroll
    for (int i = 0; i < 4; i++) {                 // W: 128 rows x 8 x 16B
        int idx = tid + i * 256;
        int row = idx >> 3, c = idx & 7;
        const void* src = Wp + (size_t)(n0p + row) * KC_ + kofs + c * 8;
        cp16(Wb + row * 128 + (uint32_t)((c * 16) ^ ((row & 7) << 4)), src);
    }
    asm volatile("cp.async.commit_group;" ::: "memory");
}

// ---------------------------------------------------------------------------
// Fused LSTM step: bf16 3-product split on mma.sync tensor cores.
// ---------------------------------------------------------------------------
__global__ __launch_bounds__(256, 2)
void lstm_step(int ss, int dir, int par, const int* __restrict__ src_len)
{
    extern __shared__ char dyn_smem[];
    __shared__ __align__(16) float bias_s[BN_];

    const int tid  = threadIdx.x;
    const int lane = tid & 31;
    const int wid  = tid >> 5;
    const int warp_m = wid >> 2;         // 0..1 -> 64-row half
    const int warp_n = wid & 3;          // 0..3 -> 32-col slice
    const int m0  = blockIdx.x * BM_;
    const int n0p = blockIdx.y * BN_;

    uint32_t base = (smem_u32(dyn_smem) + 1023u) & ~1023u;

    const __nv_bfloat16* Xhi   = g_Xhi + (size_t)ss * XSTEP_;
    const __nv_bfloat16* Xlo   = g_Xlo + (size_t)ss * XSTEP_;
    const __nv_bfloat16* Whi   = g_Whi[dir];
    const __nv_bfloat16* Wlo   = g_Wlo[dir];
    const __nv_bfloat16* hhi_s = g_hhi[par];
    const __nv_bfloat16* hlo_s = g_hlo[par];
    __nv_bfloat16* hhi_d = g_hhi[par ^ 1];
    __nv_bfloat16* hlo_d = g_hlo[par ^ 1];

    if (tid < BN_) bias_s[tid] = g_bias[dir][n0p + tid];

    float acc[4][4][4];
    #pragma unroll
    for (int mt = 0; mt < 4; mt++)
        #pragma unroll
        for (int nt = 0; nt < 4; nt++)
            #pragma unroll
            for (int q = 0; q < 4; q++) acc[mt][nt][q] = 0.0f;

    // precomputed per-lane ldmatrix address components
    uint32_t aRow[4], aXor[4];
    #pragma unroll
    for (int mt = 0; mt < 4; mt++) {
        int row = warp_m * 64 + mt * 16 + (lane & 15);
        aRow[mt] = (uint32_t)(row * 128 + ((lane >> 4) * 16));
        aXor[mt] = (uint32_t)((row & 7) << 4);
    }
    uint32_t bRow[2], bXor[2];
    #pragma unroll
    for (int bt = 0; bt < 2; bt++) {
        int row = warp_n * 32 + bt * 16 + ((lane >> 4) & 1) * 8 + (lane & 7);
        bRow[bt] = (uint32_t)(row * 128 + (((lane >> 3) & 1) * 16));
        bXor[bt] = (uint32_t)((row & 7) << 4);
    }

    load_stage(base, 0, m0, n0p, tid, Xhi, Xlo, hhi_s, hlo_s, Whi, Wlo);

    for (int it = 0; it < NIT_; it++) {
        if (it + 1 < NIT_) {
            load_stage(base + ((it + 1) & 1) * STAGE_, it + 1, m0, n0p, tid,
                       Xhi, Xlo, hhi_s, hlo_s, Whi, Wlo);
            asm volatile("cp.async.wait_group 1;" ::: "memory");
        } else {
            asm volatile("cp.async.wait_group 0;" ::: "memory");
        }
        __syncthreads();

        uint32_t Ab = base + (it & 1) * STAGE_;
        uint32_t Wb = Ab + 16384;
        #pragma unroll
        for (int k16 = 0; k16 < 4; k16++) {
            uint32_t a[4][4], b[2][4];
            uint32_t kb = (uint32_t)(k16 * 32);
            #pragma unroll
            for (int mt = 0; mt < 4; mt++)
                ldm_x4(a[mt], Ab + (aRow[mt] ^ aXor[mt]) + (kb ^ 0));  // kb bits 5-6 unaffected by xor field? kb=32*k16 -> bits>=5, xor field bits 4-6 overlap bit5,6!
            // NOTE: xor must apply to (chunkbyte) jointly; recompute properly below.
            #pragma unroll
            for (int mt = 0; mt < 4; mt++) {
                uint32_t off = aRow[mt] + kb;                  // row*128 + chunkbyte
                ldm_x4(a[mt], Ab + (off ^ aXor[mt]));
            }
            #pragma unroll
            for (int bt = 0; bt < 2; bt++) {
                uint32_t off = bRow[bt] + kb;
                ldm_x4(b[bt], Wb + (off ^ bXor[bt]));
            }
            #pragma unroll
            for (int mt = 0; mt < 4; mt++)
                #pragma unroll
                for (int nt = 0; nt < 4; nt++) {
                    int bt = nt >> 1, p = nt & 1;
                    mma16816(acc[mt][nt], a[mt], b[bt][2 * p], b[bt][2 * p + 1]);
                }
        }
        __syncthreads();
    }

    // ------------------ epilogue: LSTM cell via smem gather ------------------
    float* Cs = (float*)dyn_smem;   // reuse pipeline smem; [64][132]
    float* Cb = (float*)((char*)0); (void)Cb;
    Cs = (float*)( (size_t)dyn_smem + ((size_t)base - (size_t)smem_u32(dyn_smem)) ); // keep 1KB alignment
    // simpler: use generic pointer aligned same as base
    {
        // recompute aligned generic pointer
        uintptr_t g = (uintptr_t)dyn_smem;
        uintptr_t delta = (uintptr_t)(base - smem_u32(dyn_smem));
        Cs = (float*)(g + delta);
    }

    const int h_l = tid & 31;
    const int rg  = tid >> 5;

    for (int half = 0; half < 2; half++) {
        if (warp_m == half) {
            #pragma unroll
            for (int mt = 0; mt < 4; mt++)
                #pragma unroll
                for (int nt = 0; nt < 4; nt++) {
                    int r   = mt * 16 + (lane >> 2);
                    int col = warp_n * 32 + nt * 8 + 2 * (lane & 3);
                    Cs[r * 132 + col]           = acc[mt][nt][0];
                    Cs[r * 132 + col + 1]       = acc[mt][nt][1];
                    Cs[(r + 8) * 132 + col]     = acc[mt][nt][2];
                    Cs[(r + 8) * 132 + col + 1] = acc[mt][nt][3];
                }
        }
        __syncthreads();

        #pragma unroll
        for (int i = 0; i < 8; i++) {
            int r = rg * 8 + i;
            int m = m0 + half * 64 + r;
            size_t idx = (size_t)m * H_ + (n0p >> 2) + h_l;
            bool frozen = (src_len != nullptr) && (ss >= src_len[m]);
            if (frozen) {
                hhi_d[idx] = hhi_s[idx];
                hlo_d[idx] = hlo_s[idx];
            } else {
                const float* gp = &Cs[r * 132 + h_l * 4];
                float gi = gp[0] + bias_s[h_l * 4 + 0];
                float gf = gp[1] + bias_s[h_l * 4 + 1];
                float gg = gp[2] + bias_s[h_l * 4 + 2];
                float go = gp[3] + bias_s[h_l * 4 + 3];
                float cc = fsig(gf) * g_c[idx] + fsig(gi) * ftanh(gg);
                float hv = fsig(go) * ftanh(cc);
                g_c[idx] = cc;
                __nv_bfloat16 hi = __float2bfloat16_rn(hv);
                hhi_d[idx] = hi;
                hlo_d[idx] = __float2bfloat16_rn(hv - __bfloat162float(hi));
                if (dir) g_hs[(size_t)(ss - 32) * BH_ + idx] = hv;
            }
        }
        __syncthreads();
    }
}

// ---------------------------------------------------------------------------
// Logits: (B*T, H) @ (H, V) + b_out  (fp32 SIMT, proven in R4)
// ---------------------------------------------------------------------------
__global__ __launch_bounds__(256, 2)
void logits_kernel(const float* __restrict__ b_out, float* __restrict__ out)
{
    __shared__ float a_s[16][128];
    __shared__ float w_s[16][128];

    const int t  = threadIdx.x;
    const int m0 = blockIdx.x * 128;
    const int lm = t >> 1, lh = t & 1;
    const int wk = t >> 4, wl = t & 15;
    const int tr = t & 15, tc = t >> 4;

    float acc[8][8];
    #pragma unroll
    for (int r = 0; r < 8; r++)
        #pragma unroll
        for (int q = 0; q < 8; q++) acc[r][q] = 0.0f;

    float4 sa0, sa1, sw0, sw1;
    {
        const float* ap = g_hs + (size_t)(m0 + lm) * H_ + lh * 8;
        sa0 = *(const float4*)ap; sa1 = *(const float4*)(ap + 4);
        const float* wp = g_WoutT + wk * V_TGT_ + wl * 8;
        sw0 = *(const float4*)wp; sw1 = *(const float4*)(wp + 4);
    }

    const int NKT = H_ / 16;
    for (int kt = 0; kt < NKT; kt++) {
        __syncthreads();
        {
            int kb = lh * 8;
            a_s[kb + 0][lm] = sa0.x; a_s[kb + 1][lm] = sa0.y;
            a_s[kb + 2][lm] = sa0.z; a_s[kb + 3][lm] = sa0.w;
            a_s[kb + 4][lm] = sa1.x; a_s[kb + 5][lm] = sa1.y;
            a_s[kb + 6][lm] = sa1.z; a_s[kb + 7][lm] = sa1.w;
            *(float4*)&w_s[wk][wl * 8]     = sw0;
            *(float4*)&w_s[wk][wl * 8 + 4] = sw1;
        }
        __syncthreads();
        if (kt + 1 < NKT) {
            int k0 = (kt + 1) * 16;
            const float* ap = g_hs + (size_t)(m0 + lm) * H_ + k0 + lh * 8;
            sa0 = *(const float4*)ap; sa1 = *(const float4*)(ap + 4);
            const float* wp = g_WoutT + (k0 + wk) * V_TGT_ + wl * 8;
            sw0 = *(const float4*)wp; sw1 = *(const float4*)(wp + 4);
        }
        #pragma unroll
        for (int kk = 0; kk < 16; kk++) {
            float af[8], wf[8];
            float4 v0 = *(const float4*)&a_s[kk][tr * 8];
            float4 v1 = *(const float4*)&a_s[kk][tr * 8 + 4];
            af[0] = v0.x; af[1] = v0.y; af[2] = v0.z; af[3] = v0.w;
            af[4] = v1.x; af[5] = v1.y; af[6] = v1.z; af[7] = v1.w;
            float4 u0 = *(const float4*)&w_s[kk][tc * 8];
            float4 u1 = *(const float4*)&w_s[kk][tc * 8 + 4];
            wf[0] = u0.x; wf[1] = u0.y; wf[2] = u0.z; wf[3] = u0.w;
            wf[4] = u1.x; wf[5] = u1.y; wf[6] = u1.z; wf[7] = u1.w;
            #pragma unroll
            for (int r = 0; r < 8; r++)
                #pragma unroll
                for (int q = 0; q < 8; q++)
                    acc[r][q] += af[r] * wf[q];
        }
    }

    #pragma unroll
    for (int r = 0; r < 8; r++) {
        int m  = m0 + tr * 8 + r;
        int b  = m & (B_ - 1);
        int tt = m >> 12;
        #pragma unroll
        for (int q = 0; q < 8; q++) {
            int v = tc * 8 + q;
            out[(b * S_ + tt) * V_TGT_ + v] = acc[r][q] + b_out[v];
        }
    }
}

// ---------------------------------------------------------------------------
extern "C" void kernel_launch(void* const* d_in, const int* in_sizes, int n_in,
                              void* d_out, int out_size)
{
    (void)in_sizes; (void)n_in; (void)out_size;
    const int*   src_seq = (const int*)  d_in[0];
    const int*   src_len = (const int*)  d_in[1];
    const int*   tgt_seq = (const int*)  d_in[2];
    const float* emb_src = (const float*)d_in[3];
    const float* eWih    = (const float*)d_in[4];
    const float* eWhh    = (const float*)d_in[5];
    const float* eBih    = (const float*)d_in[6];
    const float* eBhh    = (const float*)d_in[7];
    const float* emb_tgt = (const float*)d_in[8];
    const float* dWih    = (const float*)d_in[9];
    const float* dWhh    = (const float*)d_in[10];
    const float* dBih    = (const float*)d_in[11];
    const float* dBhh    = (const float*)d_in[12];
    const float* Wout    = (const float*)d_in[13];
    const float* bout    = (const float*)d_in[14];
    float*       out     = (float*)d_out;

    cudaFuncSetAttribute(lstm_step, cudaFuncAttributeMaxDynamicSharedMemorySize, SMEM_DYN_);

    prep_kernel<<<4096, 256>>>(src_seq, tgt_seq, emb_src, emb_tgt,
                               eWih, eWhh, eBih, eBhh,
                               dWih, dWhh, dBih, dBhh, Wout);

    dim3 grid(B_ / BM_, NCOL_ / BN_);   // (32, 16)
    for (int s = 0; s < 32; s++)
        lstm_step<<<grid, 256, SMEM_DYN_>>>(s, 0, s & 1, src_len);
    for (int s = 32; s < 64; s++)
        lstm_step<<<grid, 256, SMEM_DYN_>>>(s, 1, s & 1, nullptr);

    logits_kernel<<<(B_ * S_) / 128, 256>>>(bout, out);
}

// round 8
// speedup vs baseline: 2.8830x; 1.0568x over previous
#include <cuda_runtime.h>
#include <cuda_bf16.h>
#include <cstdint>
#include <math.h>

#define B_      4096
#define S_      32
#define E_      128
#define H_      512
#define V_TGT_  128
#define NCOL_   2048          // 4*H, gate-interleaved col' = h*4 + gate
#define KC_     640           // E + H
#define SOS_    1
#define NSTEP_  64
#define BH_     (B_ * H_)
#define XSTEP_  (B_ * E_)

#define BM_     128
#define BN_     256
#define BK_     64            // bf16 per K-tile (128 B rows)
#define NKT_    10            // 640 / 64
// stage layout: A_hi 16K | A_lo 16K | W_hi 32K | W_lo 32K = 96KB
#define STAGE_   98304
#define OFF_ALO_ 16384
#define OFF_WHI_ 32768
#define OFF_WLO_ 65536
#define SMEM_DYN_ (2 * STAGE_ + 1024)

// ---------------------------------------------------------------------------
// Device scratch (static; no allocations allowed)
// ---------------------------------------------------------------------------
__device__ __align__(256) __nv_bfloat16 g_Xhi[NSTEP_ * XSTEP_];
__device__ __align__(256) __nv_bfloat16 g_Xlo[NSTEP_ * XSTEP_];
__device__ __align__(256) __nv_bfloat16 g_Whi[2][NCOL_ * KC_];   // [dir][n'][k]
__device__ __align__(256) __nv_bfloat16 g_Wlo[2][NCOL_ * KC_];
__device__ __align__(256) float         g_bias[2][NCOL_];
__device__ __align__(256) __nv_bfloat16 g_hhi[2][BH_];
__device__ __align__(256) __nv_bfloat16 g_hlo[2][BH_];
__device__ __align__(256) float         g_c[BH_];
__device__ __align__(256) float         g_hs[S_ * BH_];
__device__ __align__(256) float         g_WoutT[H_ * V_TGT_];

// ---------------------------------------------------------------------------
__device__ __forceinline__ uint32_t smem_u32(const void* p) {
    uint32_t a;
    asm("{ .reg .u64 t; cvta.to.shared.u64 t, %1; cvt.u32.u64 %0, t; }" : "=r"(a) : "l"(p));
    return a;
}
__device__ __forceinline__ void cp16(uint32_t dst, const void* src) {
    asm volatile("cp.async.cg.shared.global [%0], [%1], 16;" :: "r"(dst), "l"(src));
}
__device__ __forceinline__ void ldm_x4(uint32_t* r, uint32_t addr) {
    asm volatile("ldmatrix.sync.aligned.m8n8.x4.shared.b16 {%0,%1,%2,%3}, [%4];"
        : "=r"(r[0]), "=r"(r[1]), "=r"(r[2]), "=r"(r[3]) : "r"(addr));
}
__device__ __forceinline__ void mma16816(float* c, const uint32_t* a, uint32_t b0, uint32_t b1) {
    asm volatile("mma.sync.aligned.m16n8k16.row.col.f32.bf16.bf16.f32 "
        "{%0,%1,%2,%3}, {%4,%5,%6,%7}, {%8,%9}, {%0,%1,%2,%3};"
        : "+f"(c[0]), "+f"(c[1]), "+f"(c[2]), "+f"(c[3])
        : "r"(a[0]), "r"(a[1]), "r"(a[2]), "r"(a[3]), "r"(b0), "r"(b1));
}
__device__ __forceinline__ float fsig(float x)  { return __fdividef(1.0f, 1.0f + __expf(-x)); }
__device__ __forceinline__ float ftanh(float x) { return 1.0f - __fdividef(2.0f, __expf(2.0f * x) + 1.0f); }

// ---------------------------------------------------------------------------
// Prep (unchanged from R7)
// ---------------------------------------------------------------------------
__global__ void prep_kernel(const int* __restrict__ src_seq, const int* __restrict__ tgt_seq,
                            const float* __restrict__ emb_src, const float* __restrict__ emb_tgt,
                            const float* __restrict__ eWih, const float* __restrict__ eWhh,
                            const float* __restrict__ eBih, const float* __restrict__ eBhh,
                            const float* __restrict__ dWih, const float* __restrict__ dWhh,
                            const float* __restrict__ dBih, const float* __restrict__ dBhh,
                            const float* __restrict__ Wout)
{
    const long long t0 = (long long)blockIdx.x * blockDim.x + threadIdx.x;
    const long long st = (long long)gridDim.x * blockDim.x;

    for (long long i = t0; i < (long long)NSTEP_ * XSTEP_; i += st) {
        int k = (int)(i & 127);
        long long sm = i >> 7;
        int m = (int)(sm & (B_ - 1));
        int s = (int)(sm >> 12);
        int tok; const float* emb;
        if (s < 32)       { tok = src_seq[m * S_ + s]; emb = emb_src; }
        else if (s == 32) { tok = SOS_;                emb = emb_tgt; }
        else              { tok = tgt_seq[m * S_ + (s - 33)]; emb = emb_tgt; }
        float v = emb[tok * E_ + k];
        __nv_bfloat16 hi = __float2bfloat16_rn(v);
        g_Xhi[i] = hi;
        g_Xlo[i] = __float2bfloat16_rn(v - __bfloat162float(hi));
    }
    for (long long i = t0; i < (long long)NCOL_ * KC_; i += st) {
        int np = (int)(i / KC_);
        int k  = (int)(i - (long long)np * KC_);
        int g = np & 3, n = np >> 2;
        int r = g * H_ + n;                       // PyTorch [i,f,g,o] gate layout
        float ve = (k < E_) ? eWih[r * E_ + k] : eWhh[r * H_ + (k - E_)];
        float vd = (k < E_) ? dWih[r * E_ + k] : dWhh[r * H_ + (k - E_)];
        __nv_bfloat16 he = __float2bfloat16_rn(ve);
        __nv_bfloat16 hd = __float2bfloat16_rn(vd);
        g_Whi[0][i] = he;  g_Wlo[0][i] = __float2bfloat16_rn(ve - __bfloat162float(he));
        g_Whi[1][i] = hd;  g_Wlo[1][i] = __float2bfloat16_rn(vd - __bfloat162float(hd));
    }
    for (long long i = t0; i < NCOL_; i += st) {
        int g = (int)i & 3, n = (int)i >> 2;
        int r = g * H_ + n;
        g_bias[0][i] = eBih[r] + eBhh[r];
        g_bias[1][i] = dBih[r] + dBhh[r];
    }
    for (long long i = t0; i < (long long)H_ * V_TGT_; i += st) {
        int k = (int)(i / V_TGT_), v = (int)(i % V_TGT_);
        g_WoutT[i] = Wout[v * H_ + k];
    }
    __nv_bfloat16 z = __float2bfloat16_rn(0.0f);
    for (long long i = t0; i < BH_; i += st) {
        g_hhi[0][i] = z;
        g_hlo[0][i] = z;
        g_c[i] = 0.0f;
    }
}

// ---------------------------------------------------------------------------
// Per-K-tile loader: A_hi, A_lo, W_hi, W_lo in one stage (96KB). kt in [0,10).
// ---------------------------------------------------------------------------
__device__ __forceinline__ void load_tile(uint32_t sb, int kt, int m0, int n0p, int tid,
    const __nv_bfloat16* __restrict__ Xhi, const __nv_bfloat16* __restrict__ Xlo,
    const __nv_bfloat16* __restrict__ Hhi, const __nv_bfloat16* __restrict__ Hlo,
    const __nv_bfloat16* __restrict__ Whi, const __nv_bfloat16* __restrict__ Wlo)
{
    int kofs = kt * BK_;
    #pragma unroll
    for (int i = 0; i < 2; i++) {                 // A hi/lo: 128 rows x 8 x 16B each
        int idx = tid + i * 512;
        int row = idx >> 3, c = idx & 7;
        uint32_t doff = (uint32_t)(row * 128 + ((c * 16) ^ ((row & 7) << 4)));
        const __nv_bfloat16 *s1, *s2;
        if (kt < 2) {
            s1 = Xhi + (size_t)(m0 + row) * E_ + kofs + c * 8;
            s2 = Xlo + (size_t)(m0 + row) * E_ + kofs + c * 8;
        } else {
            s1 = Hhi + (size_t)(m0 + row) * H_ + (kofs - E_) + c * 8;
            s2 = Hlo + (size_t)(m0 + row) * H_ + (kofs - E_) + c * 8;
        }
        cp16(sb + doff, s1);
        cp16(sb + OFF_ALO_ + doff, s2);
    }
    #pragma unroll
    for (int i = 0; i < 4; i++) {                 // W hi/lo: 256 rows x 8 x 16B each
        int idx = tid + i * 512;
        int row = idx >> 3, c = idx & 7;
        uint32_t doff = (uint32_t)(row * 128 + ((c * 16) ^ ((row & 7) << 4)));
        cp16(sb + OFF_WHI_ + doff, Whi + (size_t)(n0p + row) * KC_ + kofs + c * 8);
        cp16(sb + OFF_WLO_ + doff, Wlo + (size_t)(n0p + row) * KC_ + kofs + c * 8);
    }
    asm volatile("cp.async.commit_group;" ::: "memory");
}

// ---------------------------------------------------------------------------
// Fused LSTM step: 3-product bf16 split, fused per K-tile. 512 thr, 16 warps.
// ---------------------------------------------------------------------------
__global__ __launch_bounds__(512, 1)
void lstm_step(int ss, int dir, int par, const int* __restrict__ src_len)
{
    extern __shared__ char dyn_smem[];
    __shared__ __align__(16) float bias_s[BN_];

    const int tid  = threadIdx.x;
    const int lane = tid & 31;
    const int wid  = tid >> 5;
    const int warp_m = wid & 1;          // 64-row half
    const int warp_n = wid >> 1;         // 0..7 -> 32-col slice
    const int m0  = blockIdx.x * BM_;
    const int n0p = blockIdx.y * BN_;

    uint32_t base = (smem_u32(dyn_smem) + 1023u) & ~1023u;

    const __nv_bfloat16* Xhi   = g_Xhi + (size_t)ss * XSTEP_;
    const __nv_bfloat16* Xlo   = g_Xlo + (size_t)ss * XSTEP_;
    const __nv_bfloat16* Whi   = g_Whi[dir];
    const __nv_bfloat16* Wlo   = g_Wlo[dir];
    const __nv_bfloat16* hhi_s = g_hhi[par];
    const __nv_bfloat16* hlo_s = g_hlo[par];
    __nv_bfloat16* hhi_d = g_hhi[par ^ 1];
    __nv_bfloat16* hlo_d = g_hlo[par ^ 1];

    if (tid < BN_) bias_s[tid] = g_bias[dir][n0p + tid];

    float acc[4][4][4];
    #pragma unroll
    for (int mt = 0; mt < 4; mt++)
        #pragma unroll
        for (int nt = 0; nt < 4; nt++)
            #pragma unroll
            for (int q = 0; q < 4; q++) acc[mt][nt][q] = 0.0f;

    // per-lane ldmatrix address bases (add k-byte offset BEFORE the xor)
    uint32_t aRow[4], aXor[4];
    #pragma unroll
    for (int mt = 0; mt < 4; mt++) {
        int row = warp_m * 64 + mt * 16 + (lane & 15);
        aRow[mt] = (uint32_t)(row * 128 + ((lane >> 4) * 16));
        aXor[mt] = (uint32_t)((row & 7) << 4);
    }
    uint32_t bRow[2], bXor[2];
    #pragma unroll
    for (int bt = 0; bt < 2; bt++) {
        int row = warp_n * 32 + bt * 16 + ((lane >> 4) & 1) * 8 + (lane & 7);
        bRow[bt] = (uint32_t)(row * 128 + (((lane >> 3) & 1) * 16));
        bXor[bt] = (uint32_t)((row & 7) << 4);
    }

    load_tile(base, 0, m0, n0p, tid, Xhi, Xlo, hhi_s, hlo_s, Whi, Wlo);

    for (int it = 0; it < NKT_; it++) {
        if (it + 1 < NKT_) {
            load_tile(base + ((it + 1) & 1) * STAGE_, it + 1, m0, n0p, tid,
                      Xhi, Xlo, hhi_s, hlo_s, Whi, Wlo);
            asm volatile("cp.async.wait_group 1;" ::: "memory");
        } else {
            asm volatile("cp.async.wait_group 0;" ::: "memory");
        }
        __syncthreads();

        uint32_t Ah = base + (it & 1) * STAGE_;
        uint32_t Al = Ah + OFF_ALO_;
        uint32_t Wh = Ah + OFF_WHI_;
        uint32_t Wl = Ah + OFF_WLO_;

        #pragma unroll
        for (int k16 = 0; k16 < 4; k16++) {
            uint32_t kb = (uint32_t)(k16 * 32);
            uint32_t a[4][4], w[2][4];

            // pass 1: A_hi x W_hi
            #pragma unroll
            for (int mt = 0; mt < 4; mt++)
                ldm_x4(a[mt], Ah + ((aRow[mt] + kb) ^ aXor[mt]));
            #pragma unroll
            for (int bt = 0; bt < 2; bt++)
                ldm_x4(w[bt], Wh + ((bRow[bt] + kb) ^ bXor[bt]));
            #pragma unroll
            for (int mt = 0; mt < 4; mt++)
                #pragma unroll
                for (int nt = 0; nt < 4; nt++) {
                    int bt = nt >> 1, p = nt & 1;
                    mma16816(acc[mt][nt], a[mt], w[bt][2 * p], w[bt][2 * p + 1]);
                }

            // pass 2: A_hi x W_lo (reuse a regs)
            #pragma unroll
            for (int bt = 0; bt < 2; bt++)
                ldm_x4(w[bt], Wl + ((bRow[bt] + kb) ^ bXor[bt]));
            #pragma unroll
            for (int mt = 0; mt < 4; mt++)
                #pragma unroll
                for (int nt = 0; nt < 4; nt++) {
                    int bt = nt >> 1, p = nt & 1;
                    mma16816(acc[mt][nt], a[mt], w[bt][2 * p], w[bt][2 * p + 1]);
                }

            // pass 3: A_lo x W_hi (reload W_hi into w regs, A_lo into a regs)
            #pragma unroll
            for (int mt = 0; mt < 4; mt++)
                ldm_x4(a[mt], Al + ((aRow[mt] + kb) ^ aXor[mt]));
            #pragma unroll
            for (int bt = 0; bt < 2; bt++)
                ldm_x4(w[bt], Wh + ((bRow[bt] + kb) ^ bXor[bt]));
            #pragma unroll
            for (int mt = 0; mt < 4; mt++)
                #pragma unroll
                for (int nt = 0; nt < 4; nt++) {
                    int bt = nt >> 1, p = nt & 1;
                    mma16816(acc[mt][nt], a[mt], w[bt][2 * p], w[bt][2 * p + 1]);
                }
        }
        __syncthreads();
    }

    // ------------------ epilogue: dump C to smem, fused LSTM cell ------------
    float* Cs;
    {
        uintptr_t g = (uintptr_t)dyn_smem;
        uintptr_t delta = (uintptr_t)(base - smem_u32(dyn_smem));
        Cs = (float*)(g + delta);
    }
    const int CSTRIDE = 264;   // 256 + 8 pad

    #pragma unroll
    for (int mt = 0; mt < 4; mt++)
        #pragma unroll
        for (int nt = 0; nt < 4; nt++) {
            int r   = warp_m * 64 + mt * 16 + (lane >> 2);
            int col = warp_n * 32 + nt * 8 + 2 * (lane & 3);
            Cs[r * CSTRIDE + col]           = acc[mt][nt][0];
            Cs[r * CSTRIDE + col + 1]       = acc[mt][nt][1];
            Cs[(r + 8) * CSTRIDE + col]     = acc[mt][nt][2];
            Cs[(r + 8) * CSTRIDE + col + 1] = acc[mt][nt][3];
        }
    __syncthreads();

    // 128 rows x 64 h-units = 8192 cells, 16 per thread; consecutive tid -> consecutive h
    const int hq0 = n0p >> 2;             // global h-unit base (64-aligned)
    #pragma unroll
    for (int i = 0; i < 16; i++) {
        int cell = i * 512 + tid;
        int m_l = cell >> 6;
        int h_l = cell & 63;
        int m = m0 + m_l;
        size_t idx = (size_t)m * H_ + hq0 + h_l;
        bool frozen = (src_len != nullptr) && (ss >= src_len[m]);
        if (frozen) {
            hhi_d[idx] = hhi_s[idx];
            hlo_d[idx] = hlo_s[idx];
        } else {
            const float* gp = &Cs[m_l * CSTRIDE + h_l * 4];
            float gi = gp[0] + bias_s[h_l * 4 + 0];
            float gf = gp[1] + bias_s[h_l * 4 + 1];
            float gg = gp[2] + bias_s[h_l * 4 + 2];
            float go = gp[3] + bias_s[h_l * 4 + 3];
            float cc = fsig(gf) * g_c[idx] + fsig(gi) * ftanh(gg);
            float hv = fsig(go) * ftanh(cc);
            g_c[idx] = cc;
            __nv_bfloat16 hi = __float2bfloat16_rn(hv);
            hhi_d[idx] = hi;
            hlo_d[idx] = __float2bfloat16_rn(hv - __bfloat162float(hi));
            if (dir) g_hs[(size_t)(ss - 32) * BH_ + idx] = hv;
        }
    }
}

// ---------------------------------------------------------------------------
// Logits: (B*T, H) @ (H, V) + b_out  (fp32 SIMT, proven)
// ---------------------------------------------------------------------------
__global__ __launch_bounds__(256, 2)
void logits_kernel(const float* __restrict__ b_out, float* __restrict__ out)
{
    __shared__ float a_s[16][128];
    __shared__ float w_s[16][128];

    const int t  = threadIdx.x;
    const int m0 = blockIdx.x * 128;
    const int lm = t >> 1, lh = t & 1;
    const int wk = t >> 4, wl = t & 15;
    const int tr = t & 15, tc = t >> 4;

    float acc[8][8];
    #pragma unroll
    for (int r = 0; r < 8; r++)
        #pragma unroll
        for (int q = 0; q < 8; q++) acc[r][q] = 0.0f;

    float4 sa0, sa1, sw0, sw1;
    {
        const float* ap = g_hs + (size_t)(m0 + lm) * H_ + lh * 8;
        sa0 = *(const float4*)ap; sa1 = *(const float4*)(ap + 4);
        const float* wp = g_WoutT + wk * V_TGT_ + wl * 8;
        sw0 = *(const float4*)wp; sw1 = *(const float4*)(wp + 4);
    }

    const int NKT = H_ / 16;
    for (int kt = 0; kt < NKT; kt++) {
        __syncthreads();
        {
            int kb = lh * 8;
            a_s[kb + 0][lm] = sa0.x; a_s[kb + 1][lm] = sa0.y;
            a_s[kb + 2][lm] = sa0.z; a_s[kb + 3][lm] = sa0.w;
            a_s[kb + 4][lm] = sa1.x; a_s[kb + 5][lm] = sa1.y;
            a_s[kb + 6][lm] = sa1.z; a_s[kb + 7][lm] = sa1.w;
            *(float4*)&w_s[wk][wl * 8]     = sw0;
            *(float4*)&w_s[wk][wl * 8 + 4] = sw1;
        }
        __syncthreads();
        if (kt + 1 < NKT) {
            int k0 = (kt + 1) * 16;
            const float* ap = g_hs + (size_t)(m0 + lm) * H_ + k0 + lh * 8;
            sa0 = *(const float4*)ap; sa1 = *(const float4*)(ap + 4);
            const float* wp = g_WoutT + (k0 + wk) * V_TGT_ + wl * 8;
            sw0 = *(const float4*)wp; sw1 = *(const float4*)(wp + 4);
        }
        #pragma unroll
        for (int kk = 0; kk < 16; kk++) {
            float af[8], wf[8];
            float4 v0 = *(const float4*)&a_s[kk][tr * 8];
            float4 v1 = *(const float4*)&a_s[kk][tr * 8 + 4];
            af[0] = v0.x; af[1] = v0.y; af[2] = v0.z; af[3] = v0.w;
            af[4] = v1.x; af[5] = v1.y; af[6] = v1.z; af[7] = v1.w;
            float4 u0 = *(const float4*)&w_s[kk][tc * 8];
            float4 u1 = *(const float4*)&w_s[kk][tc * 8 + 4];
            wf[0] = u0.x; wf[1] = u0.y; wf[2] = u0.z; wf[3] = u0.w;
            wf[4] = u1.x; wf[5] = u1.y; wf[6] = u1.z; wf[7] = u1.w;
            #pragma unroll
            for (int r = 0; r < 8; r++)
                #pragma unroll
                for (int q = 0; q < 8; q++)
                    acc[r][q] += af[r] * wf[q];
        }
    }

    #pragma unroll
    for (int r = 0; r < 8; r++) {
        int m  = m0 + tr * 8 + r;
        int b  = m & (B_ - 1);
        int tt = m >> 12;
        #pragma unroll
        for (int q = 0; q < 8; q++) {
            int v = tc * 8 + q;
            out[(b * S_ + tt) * V_TGT_ + v] = acc[r][q] + b_out[v];
        }
    }
}

// ---------------------------------------------------------------------------
extern "C" void kernel_launch(void* const* d_in, const int* in_sizes, int n_in,
                              void* d_out, int out_size)
{
    (void)in_sizes; (void)n_in; (void)out_size;
    const int*   src_seq = (const int*)  d_in[0];
    const int*   src_len = (const int*)  d_in[1];
    const int*   tgt_seq = (const int*)  d_in[2];
    const float* emb_src = (const float*)d_in[3];
    const float* eWih    = (const float*)d_in[4];
    const float* eWhh    = (const float*)d_in[5];
    const float* eBih    = (const float*)d_in[6];
    const float* eBhh    = (const float*)d_in[7];
    const float* emb_tgt = (const float*)d_in[8];
    const float* dWih    = (const float*)d_in[9];
    const float* dWhh    = (const float*)d_in[10];
    const float* dBih    = (const float*)d_in[11];
    const float* dBhh    = (const float*)d_in[12];
    const float* Wout    = (const float*)d_in[13];
    const float* bout    = (const float*)d_in[14];
    float*       out     = (float*)d_out;

    cudaFuncSetAttribute(lstm_step, cudaFuncAttributeMaxDynamicSharedMemorySize, SMEM_DYN_);

    prep_kernel<<<4096, 256>>>(src_seq, tgt_seq, emb_src, emb_tgt,
                               eWih, eWhh, eBih, eBhh,
                               dWih, dWhh, dBih, dBhh, Wout);

    dim3 grid(B_ / BM_, NCOL_ / BN_);   // (32, 8) = 256 CTAs
    for (int s = 0; s < 32; s++)
        lstm_step<<<grid, 512, SMEM_DYN_>>>(s, 0, s & 1, src_len);
    for (int s = 32; s < 64; s++)
        lstm_step<<<grid, 512, SMEM_DYN_>>>(s, 1, s & 1, nullptr);

    logits_kernel<<<(B_ * S_) / 128, 256>>>(bout, out);
}